// round 1
// baseline (speedup 1.0000x reference)
#include <cuda_runtime.h>
#include <cstdint>

#define SEQ 512
#define BATCH 32
#define INP 1024
#define HID 1024
#define G4 4096
#define NLAYERS 4

// ---------------- scratch (device globals; no cudaMalloc allowed) ----------------
__device__ float g_xg[(size_t)SEQ * BATCH * G4];      // x_gates for current layer (268 MB)
__device__ float g_buf0[(size_t)SEQ * BATCH * HID];   // layer output ping (64 MB)
__device__ float g_buf1[(size_t)SEQ * BATCH * HID];   // layer output pong (64 MB)
__device__ unsigned g_cnt[SEQ];                       // per-timestep arrival counters

__global__ void init_cnt_kernel() {
    int i = blockIdx.x * blockDim.x + threadIdx.x;
    if (i < SEQ) g_cnt[i] = 0u;
}

// ---------------- input-projection GEMM: C[m,n] = X[m,:] . W[n,:] + bih[n] + bhh[n] ----
// X: [16384, 1024], W: [4096, 1024], C = g_xg [16384, 4096]
__global__ __launch_bounds__(256) void gemm_input_kernel(
    const float* __restrict__ Xext, int xsel,
    const float* __restrict__ W,
    const float* __restrict__ bih,
    const float* __restrict__ bhh)
{
    const float* __restrict__ X = (xsel == 0) ? Xext : (xsel == 1 ? g_buf0 : g_buf1);
    __shared__ float As[32][64];   // [k][m]
    __shared__ float Bs[32][64];   // [k][n]
    const int tid = threadIdx.x;
    const int tx = tid & 15, ty = tid >> 4;
    const int mB = blockIdx.y << 6;
    const int nB = blockIdx.x << 6;
    float acc[4][4] = {};

    for (int kc = 0; kc < INP; kc += 32) {
        for (int i = tid; i < 512; i += 256) {
            int row = i >> 3, k4 = (i & 7) << 2;
            float4 v = *(const float4*)&X[(size_t)(mB + row) * INP + kc + k4];
            As[k4 + 0][row] = v.x; As[k4 + 1][row] = v.y;
            As[k4 + 2][row] = v.z; As[k4 + 3][row] = v.w;
            float4 w = *(const float4*)&W[(size_t)(nB + row) * INP + kc + k4];
            Bs[k4 + 0][row] = w.x; Bs[k4 + 1][row] = w.y;
            Bs[k4 + 2][row] = w.z; Bs[k4 + 3][row] = w.w;
        }
        __syncthreads();
        #pragma unroll
        for (int k = 0; k < 32; k++) {
            float4 a = *(const float4*)&As[k][tx << 2];
            float4 b = *(const float4*)&Bs[k][ty << 2];
            acc[0][0] = fmaf(a.x, b.x, acc[0][0]); acc[0][1] = fmaf(a.x, b.y, acc[0][1]);
            acc[0][2] = fmaf(a.x, b.z, acc[0][2]); acc[0][3] = fmaf(a.x, b.w, acc[0][3]);
            acc[1][0] = fmaf(a.y, b.x, acc[1][0]); acc[1][1] = fmaf(a.y, b.y, acc[1][1]);
            acc[1][2] = fmaf(a.y, b.z, acc[1][2]); acc[1][3] = fmaf(a.y, b.w, acc[1][3]);
            acc[2][0] = fmaf(a.z, b.x, acc[2][0]); acc[2][1] = fmaf(a.z, b.y, acc[2][1]);
            acc[2][2] = fmaf(a.z, b.z, acc[2][2]); acc[2][3] = fmaf(a.z, b.w, acc[2][3]);
            acc[3][0] = fmaf(a.w, b.x, acc[3][0]); acc[3][1] = fmaf(a.w, b.y, acc[3][1]);
            acc[3][2] = fmaf(a.w, b.z, acc[3][2]); acc[3][3] = fmaf(a.w, b.w, acc[3][3]);
        }
        __syncthreads();
    }

    const int n0 = nB + (ty << 2);
    float4 b1 = *(const float4*)&bih[n0];
    float4 b2 = *(const float4*)&bhh[n0];
    float bx = b1.x + b2.x, by = b1.y + b2.y, bz = b1.z + b2.z, bw = b1.w + b2.w;
    #pragma unroll
    for (int i = 0; i < 4; i++) {
        size_t m = (size_t)(mB + (tx << 2) + i);
        float4 o;
        o.x = acc[i][0] + bx; o.y = acc[i][1] + by;
        o.z = acc[i][2] + bz; o.w = acc[i][3] + bw;
        *(float4*)&g_xg[m * G4 + n0] = o;
    }
}

// ---------------- persistent recurrence kernel ----------------
__device__ __forceinline__ void cpasync16(void* dst, const void* src) {
    unsigned s = (unsigned)__cvta_generic_to_shared(dst);
    asm volatile("cp.async.cg.shared.global [%0], [%1], 16;\n" :: "r"(s), "l"(src));
}

// 128 CTAs; CTA cb owns h-columns [cb*8, cb*8+8) => gate rows {g*1024 + cb*8 + j}.
__global__ __launch_bounds__(256) void lstm_rec_kernel(
    const float* __restrict__ Whh,    // [4096, 1024] (layer slice)
    int ysel, float* __restrict__ ysext,
    float* __restrict__ hout, float* __restrict__ cout)
{
    float* ys = (ysel == 0) ? g_buf0 : (ysel == 1 ? g_buf1 : ysext);
    __shared__ float hs[2][32][68];   // [buf][b][k]  (stride 68 floats = 272B, 16B aligned)
    __shared__ float ws[2][32][68];   // [buf][lr][k]
    __shared__ float Gs[32][33];      // [lr][b]
    __shared__ float cs[32][8];       // [b][j]
    const int tid = threadIdx.x;
    const int tx = tid & 15;          // b base: computes b = tx and tx+16
    const int ty = tid >> 4;          // lr base: computes lr = ty and ty+16
    const int c0 = blockIdx.x << 3;

    { int b = tid >> 3, j = tid & 7; cs[b][j] = 0.f; }
    __syncthreads();

    for (int t = 0; t < SEQ; t++) {
        float a00 = 0.f, a01 = 0.f, a10 = 0.f, a11 = 0.f;
        if (t > 0) {
            if (tid == 0) {
                volatile unsigned* p = &g_cnt[t - 1];
                while (*p < 128u) { __nanosleep(40); }
                __threadfence();
            }
            __syncthreads();
            const float* hsrc = ys + (size_t)(t - 1) * BATCH * HID;

            // prefetch chunk 0
            for (int i = tid; i < 1024; i += 256) {
                if (i < 512) {
                    int row = i >> 4, seg = i & 15;
                    cpasync16(&hs[0][row][seg << 2], hsrc + (size_t)row * HID + (seg << 2));
                } else {
                    int j2 = i - 512;
                    int row = j2 >> 4, seg = j2 & 15;
                    int grow = ((row >> 3) << 10) + c0 + (row & 7);
                    cpasync16(&ws[0][row][seg << 2], Whh + (size_t)grow * HID + (seg << 2));
                }
            }
            asm volatile("cp.async.commit_group;\n");

            for (int kc = 0; kc < 16; kc++) {
                if (kc + 1 < 16) {
                    int buf = (kc + 1) & 1, koff = (kc + 1) << 6;
                    for (int i = tid; i < 1024; i += 256) {
                        if (i < 512) {
                            int row = i >> 4, seg = i & 15;
                            cpasync16(&hs[buf][row][seg << 2],
                                      hsrc + (size_t)row * HID + koff + (seg << 2));
                        } else {
                            int j2 = i - 512;
                            int row = j2 >> 4, seg = j2 & 15;
                            int grow = ((row >> 3) << 10) + c0 + (row & 7);
                            cpasync16(&ws[buf][row][seg << 2],
                                      Whh + (size_t)grow * HID + koff + (seg << 2));
                        }
                    }
                    asm volatile("cp.async.commit_group;\n");
                    asm volatile("cp.async.wait_group 1;\n");
                } else {
                    asm volatile("cp.async.wait_group 0;\n");
                }
                __syncthreads();
                const int bs = kc & 1;
                #pragma unroll
                for (int k = 0; k < 64; k++) {
                    float h0 = hs[bs][tx][k];
                    float h1 = hs[bs][tx + 16][k];
                    float w0 = ws[bs][ty][k];
                    float w1 = ws[bs][ty + 16][k];
                    a00 = fmaf(h0, w0, a00);
                    a10 = fmaf(h1, w0, a10);
                    a01 = fmaf(h0, w1, a01);
                    a11 = fmaf(h1, w1, a11);
                }
                __syncthreads();
            }
        } else {
            __syncthreads();
        }

        // stage gate preactivations into smem:  Gs[lr][b]
        Gs[ty][tx]           = a00;
        Gs[ty][tx + 16]      = a10;
        Gs[ty + 16][tx]      = a01;
        Gs[ty + 16][tx + 16] = a11;
        __syncthreads();

        {
            int b = tid >> 3, j = tid & 7;
            const float* xgp = g_xg + ((size_t)t * BATCH + b) * G4 + c0 + j;
            float gi = Gs[j][b]       + xgp[0];
            float gf = Gs[8 + j][b]   + xgp[1024];
            float gg = Gs[16 + j][b]  + xgp[2048];
            float go = Gs[24 + j][b]  + xgp[3072];
            float si = 1.f / (1.f + expf(-gi));
            float sf = 1.f / (1.f + expf(-gf));
            float so = 1.f / (1.f + expf(-go));
            float tg = tanhf(gg);
            float cv = sf * cs[b][j] + si * tg;
            float hv = so * tanhf(cv);
            cs[b][j] = cv;
            ys[((size_t)t * BATCH + b) * HID + c0 + j] = hv;
            if (t == SEQ - 1) {
                hout[b * HID + c0 + j] = hv;
                cout[b * HID + c0 + j] = cv;
            }
        }
        __syncthreads();
        if (tid == 0) { __threadfence(); atomicAdd(&g_cnt[t], 1u); }
    }
}

// ---------------- host launcher ----------------
extern "C" void kernel_launch(void* const* d_in, const int* in_sizes, int n_in,
                              void* d_out, int out_size) {
    const float* x   = (const float*)d_in[0];
    const float* Wih = (const float*)d_in[1];
    const float* Whh = (const float*)d_in[2];
    const float* bih = (const float*)d_in[3];
    const float* bhh = (const float*)d_in[4];
    float* out   = (float*)d_out;
    float* hbase = out + (size_t)SEQ * BATCH * HID;                 // [L,B,H]
    float* cbase = hbase + (size_t)NLAYERS * BATCH * HID;           // [L,B,H]

    dim3 ggrid(G4 / 64, (SEQ * BATCH) / 64);
    for (int l = 0; l < NLAYERS; l++) {
        // layer IO ping-pong: l0:x->buf0, l1:buf0->buf1, l2:buf1->buf0, l3:buf0->d_out
        int xsel = (l == 0) ? 0 : ((l == 1) ? 1 : ((l == 2) ? 2 : 1));
        int ysel = (l == 0) ? 0 : ((l == 1) ? 1 : ((l == 2) ? 0 : 2));
        init_cnt_kernel<<<1, 512>>>();
        gemm_input_kernel<<<ggrid, 256>>>(x, xsel,
            Wih + (size_t)l * G4 * INP,
            bih + (size_t)l * G4,
            bhh + (size_t)l * G4);
        lstm_rec_kernel<<<128, 256>>>(Whh + (size_t)l * G4 * HID, ysel, out,
            hbase + (size_t)l * BATCH * HID,
            cbase + (size_t)l * BATCH * HID);
    }
}

// round 3
// speedup vs baseline: 1.2102x; 1.2102x over previous
#include <cuda_runtime.h>
#include <cstdint>

#define SEQ 512
#define BATCH 32
#define INP 1024
#define HID 1024
#define G4 4096
#define NLAYERS 4

typedef unsigned long long ull;

// ---------------- scratch (device globals; no cudaMalloc allowed) ----------------
__device__ float g_xg[(size_t)SEQ * BATCH * G4];      // x_gates for current layer
__device__ float g_buf0[(size_t)SEQ * BATCH * HID];   // layer output ping
__device__ float g_buf1[(size_t)SEQ * BATCH * HID];   // layer output pong
__device__ unsigned g_cnt[SEQ];                       // per-timestep arrival counters (self-resetting)

// ---------------- packed fp32 helpers ----------------
__device__ __forceinline__ ull ffma2(ull a, ull b, ull c) {
    ull d;
    asm("fma.rn.f32x2 %0, %1, %2, %3;" : "=l"(d) : "l"(a), "l"(b), "l"(c));
    return d;
}
__device__ __forceinline__ float hsum2(ull a) {
    float2 f;
    asm("mov.b64 {%0, %1}, %2;" : "=f"(f.x), "=f"(f.y) : "l"(a));
    return f.x + f.y;
}
__device__ __forceinline__ void cpasync8(void* dst, const void* src) {
    unsigned s = (unsigned)__cvta_generic_to_shared(dst);
    asm volatile("cp.async.ca.shared.global [%0], [%1], 8;\n" :: "r"(s), "l"(src));
}

// ---------------- input-projection GEMM ----------------
// C[m,n] = X[m,:]·W[n,:] + bih[n] + bhh[n];  X:[16384,1024], W:[4096,1024] -> g_xg[16384,4096]
// 64x64 tile, 256 thr, per-thread 4x4 strided-16 blocking, k-pair FFMA2.
#define GP 34   // smem pitch (floats): bank = (2*row + k) % 32 -> conflict-free
__global__ __launch_bounds__(256) void gemm_input_kernel(
    const float* __restrict__ Xext, int xsel,
    const float* __restrict__ W,
    const float* __restrict__ bih,
    const float* __restrict__ bhh)
{
    const float* __restrict__ X = (xsel == 0) ? Xext : (xsel == 1 ? g_buf0 : g_buf1);
    __shared__ float As[64 * GP];
    __shared__ float Bs[64 * GP];
    const int tid = threadIdx.x;
    const int tx = tid & 15, ty = tid >> 4;
    const int mB = blockIdx.y << 6;
    const int nB = blockIdx.x << 6;

    ull acc[4][4];
    #pragma unroll
    for (int i = 0; i < 4; i++)
        #pragma unroll
        for (int j = 0; j < 4; j++) acc[i][j] = 0ull;

    for (int kc = 0; kc < INP; kc += 32) {
        for (int u = tid; u < 512; u += 256) {
            int row = u >> 3, seg = (u & 7) << 2;
            float4 v = *(const float4*)&X[(size_t)(mB + row) * INP + kc + seg];
            float* p = As + row * GP + seg;
            p[0] = v.x; p[1] = v.y; p[2] = v.z; p[3] = v.w;
            float4 w = *(const float4*)&W[(size_t)(nB + row) * INP + kc + seg];
            float* q = Bs + row * GP + seg;
            q[0] = w.x; q[1] = w.y; q[2] = w.z; q[3] = w.w;
        }
        __syncthreads();
        #pragma unroll
        for (int kp = 0; kp < 16; kp++) {
            ull a[4], b[4];
            #pragma unroll
            for (int i = 0; i < 4; i++)
                a[i] = *(const ull*)&As[(ty + 16 * i) * GP + 2 * kp];
            #pragma unroll
            for (int j = 0; j < 4; j++)
                b[j] = *(const ull*)&Bs[(tx + 16 * j) * GP + 2 * kp];
            #pragma unroll
            for (int i = 0; i < 4; i++)
                #pragma unroll
                for (int j = 0; j < 4; j++)
                    acc[i][j] = ffma2(a[i], b[j], acc[i][j]);
        }
        __syncthreads();
    }

    float bsum[4];
    #pragma unroll
    for (int j = 0; j < 4; j++) {
        int n = nB + tx + 16 * j;
        bsum[j] = bih[n] + bhh[n];
    }
    #pragma unroll
    for (int i = 0; i < 4; i++) {
        size_t m = (size_t)(mB + ty + 16 * i);
        #pragma unroll
        for (int j = 0; j < 4; j++) {
            int n = nB + tx + 16 * j;
            g_xg[m * G4 + n] = hsum2(acc[i][j]) + bsum[j];
        }
    }
}

// ---------------- persistent recurrence kernel ----------------
// 128 CTAs; CTA cb owns h-columns [cb*8, cb*8+8) => 32 gate rows {g*1024 + cb*8 + j}.
// W_hh slice (32x1024 f32) resident in smem for all 512 steps.
#define WP 1028     // weight pitch (floats): 16B-aligned rows; conflict-free LDS.128
#define HP 258      // h pitch (floats): bank = (2*tx + k) % 32 -> conflict-free LDS.64
#define REC_SMEM_FLOATS (32 * WP + 2 * 32 * HP + 32 * 33 + 32 * 8)

__global__ __launch_bounds__(256) void lstm_rec_kernel(
    const float* __restrict__ Whh,    // [4096, 1024] (layer slice)
    int ysel, float* __restrict__ ysext,
    float* __restrict__ hout, float* __restrict__ cout)
{
    float* ys = (ysel == 0) ? g_buf0 : (ysel == 1 ? g_buf1 : ysext);
    extern __shared__ float sm[];
    float* ws = sm;                       // [32][WP]
    float* hs = ws + 32 * WP;             // [2][32][HP]
    float* Gs = hs + 2 * 32 * HP;         // [32][33]
    float* cs = Gs + 32 * 33;             // [32][8]

    const int tid = threadIdx.x;
    const int tx = tid & 15;              // batch base: b = tx, tx+16
    const int ty = tid >> 4;              // row base:   r = ty, ty+16
    const int c0 = blockIdx.x << 3;
    const int ab = tid >> 3, aj = tid & 7;   // activation mapping

    // ---- load W slice into smem once ----
    for (int u = tid; u < 8192; u += 256) {
        int r = u >> 8, s = (u & 255) << 2;
        int grow = ((r >> 3) << 10) + c0 + (r & 7);
        float4 v = *(const float4*)&Whh[(size_t)grow * HID + s];
        float* p = ws + r * WP + s;
        p[0] = v.x; p[1] = v.y; p[2] = v.z; p[3] = v.w;
    }
    cs[ab * 8 + aj] = 0.f;
    __syncthreads();

    const float* wr0 = ws + ty * WP;
    const float* wr1 = ws + (ty + 16) * WP;

    for (int t = 0; t < SEQ; t++) {
        // prefetch this step's x_gates early (independent of h)
        const float* xgp = g_xg + ((size_t)t * BATCH + ab) * G4 + c0 + aj;
        float xgi = xgp[0], xgf = xgp[1024], xgg = xgp[2048], xgo = xgp[3072];

        ull a00a = 0, a00b = 0, a01a = 0, a01b = 0;
        ull a10a = 0, a10b = 0, a11a = 0, a11b = 0;

        if (t > 0) {
            if (tid == 0) {
                volatile unsigned* p = &g_cnt[t - 1];
                while (*p < 128u) { __nanosleep(20); }
                __threadfence();
            }
            __syncthreads();
            const float* hsrc = ys + (size_t)(t - 1) * BATCH * HID;

            // prefetch chunk 0 (k = 0..255)
            for (int u = tid; u < 4096; u += 256) {
                int row = u >> 7, s2 = (u & 127) << 1;
                cpasync8(&hs[row * HP + s2], hsrc + (size_t)row * HID + s2);
            }
            asm volatile("cp.async.commit_group;\n");

            for (int kc = 0; kc < 4; kc++) {
                if (kc < 3) {
                    int buf = (kc + 1) & 1;
                    const float* src = hsrc + ((kc + 1) << 8);
                    float* dst = hs + buf * 32 * HP;
                    for (int u = tid; u < 4096; u += 256) {
                        int row = u >> 7, s2 = (u & 127) << 1;
                        cpasync8(dst + row * HP + s2, src + (size_t)row * HID + s2);
                    }
                    asm volatile("cp.async.commit_group;\n");
                    asm volatile("cp.async.wait_group 1;\n");
                } else {
                    asm volatile("cp.async.wait_group 0;\n");
                }
                __syncthreads();

                const float* hb0 = hs + (kc & 1) * 32 * HP + tx * HP;
                const float* hb1 = hs + (kc & 1) * 32 * HP + (tx + 16) * HP;
                const float* w0p = wr0 + (kc << 8);
                const float* w1p = wr1 + (kc << 8);
                #pragma unroll 8
                for (int q = 0; q < 64; q++) {
                    int k = q << 2;
                    ull h00 = *(const ull*)(hb0 + k);
                    ull h02 = *(const ull*)(hb0 + k + 2);
                    ull h10 = *(const ull*)(hb1 + k);
                    ull h12 = *(const ull*)(hb1 + k + 2);
                    ulonglong2 w0 = *(const ulonglong2*)(w0p + k);
                    ulonglong2 w1 = *(const ulonglong2*)(w1p + k);
                    a00a = ffma2(h00, w0.x, a00a);
                    a00b = ffma2(h02, w0.y, a00b);
                    a01a = ffma2(h00, w1.x, a01a);
                    a01b = ffma2(h02, w1.y, a01b);
                    a10a = ffma2(h10, w0.x, a10a);
                    a10b = ffma2(h12, w0.y, a10b);
                    a11a = ffma2(h10, w1.x, a11a);
                    a11b = ffma2(h12, w1.y, a11b);
                }
                __syncthreads();
            }
        } else {
            __syncthreads();
        }

        // stage gate preactivations: Gs[local_row][batch]
        Gs[ty * 33 + tx]             = hsum2(a00a) + hsum2(a00b);
        Gs[ty * 33 + tx + 16]        = hsum2(a10a) + hsum2(a10b);
        Gs[(ty + 16) * 33 + tx]      = hsum2(a01a) + hsum2(a01b);
        Gs[(ty + 16) * 33 + tx + 16] = hsum2(a11a) + hsum2(a11b);
        __syncthreads();

        {
            float gi = Gs[aj * 33 + ab]        + xgi;
            float gf = Gs[(8 + aj) * 33 + ab]  + xgf;
            float gg = Gs[(16 + aj) * 33 + ab] + xgg;
            float go = Gs[(24 + aj) * 33 + ab] + xgo;
            float si = 1.f / (1.f + expf(-gi));
            float sf = 1.f / (1.f + expf(-gf));
            float so = 1.f / (1.f + expf(-go));
            float tg = tanhf(gg);
            float cv = sf * cs[ab * 8 + aj] + si * tg;
            float hv = so * tanhf(cv);
            cs[ab * 8 + aj] = cv;
            ys[((size_t)t * BATCH + ab) * HID + c0 + aj] = hv;
            if (t == SEQ - 1) {
                hout[ab * HID + c0 + aj] = hv;
                cout[ab * HID + c0 + aj] = cv;
            }
        }
        __syncthreads();
        if (tid == 0) {
            __threadfence();
            unsigned old = atomicAdd(&g_cnt[t], 1u);
            // last arriver at the last step resets all counters (all waits already passed)
            if (t == SEQ - 1 && old == 127u) {
                for (int i = 0; i < SEQ; i++) g_cnt[i] = 0u;
            }
        }
    }
}

// ---------------- host launcher ----------------
extern "C" void kernel_launch(void* const* d_in, const int* in_sizes, int n_in,
                              void* d_out, int out_size) {
    const float* x   = (const float*)d_in[0];
    const float* Wih = (const float*)d_in[1];
    const float* Whh = (const float*)d_in[2];
    const float* bih = (const float*)d_in[3];
    const float* bhh = (const float*)d_in[4];
    float* out   = (float*)d_out;
    float* hbase = out + (size_t)SEQ * BATCH * HID;         // [L,B,H]
    float* cbase = hbase + (size_t)NLAYERS * BATCH * HID;   // [L,B,H]

    const int rec_smem = REC_SMEM_FLOATS * 4;
    cudaFuncSetAttribute(lstm_rec_kernel,
                         cudaFuncAttributeMaxDynamicSharedMemorySize, rec_smem);

    dim3 ggrid(G4 / 64, (SEQ * BATCH) / 64);
    for (int l = 0; l < NLAYERS; l++) {
        // layer IO ping-pong: l0:x->buf0, l1:buf0->buf1, l2:buf1->buf0, l3:buf0->d_out
        int xsel = (l == 0) ? 0 : ((l == 1) ? 1 : ((l == 2) ? 2 : 1));
        int ysel = (l == 0) ? 0 : ((l == 1) ? 1 : ((l == 2) ? 0 : 2));
        gemm_input_kernel<<<ggrid, 256>>>(x, xsel,
            Wih + (size_t)l * G4 * INP,
            bih + (size_t)l * G4,
            bhh + (size_t)l * G4);
        lstm_rec_kernel<<<128, 256, rec_smem>>>(Whh + (size_t)l * G4 * HID, ysel, out,
            hbase + (size_t)l * BATCH * HID,
            cbase + (size_t)l * BATCH * HID);
    }
}